// round 6
// baseline (speedup 1.0000x reference)
#include <cuda_runtime.h>

#define NN 50000
#define EE 800000

// Scratch (allocation-free: __device__ globals)
__device__ float g_h1[NN * 64];
__device__ float g_h2[NN * 64];
__device__ float g_agg[NN * 64];   // layer1: stride-8 atomic target; layer2/3: mean store
__device__ float g_t[NN * 32];
__device__ int   g_degi[NN];
__device__ int   g_cur[NN];
__device__ int   g_rp[NN];         // CSR row start (exclusive prefix of deg)
__device__ int   g_bsum[256];
__device__ int   g_boff[256];
__device__ int   g_csr[EE];        // src node per CSR slot

__device__ __forceinline__ void red_add_v4(float* addr, float4 v) {
    asm volatile("red.global.add.v4.f32 [%0], {%1,%2,%3,%4};"
                 :: "l"(addr), "f"(v.x), "f"(v.y), "f"(v.z), "f"(v.w)
                 : "memory");
}

// ---------------------------------------------------------------------------
__global__ void k_init() {
    int i = blockIdx.x * blockDim.x + threadIdx.x;
    if (i < NN * 8) g_agg[i] = 0.f;
    if (i < NN) { g_degi[i] = 0; g_cur[i] = 0; }
}

__global__ void k_degi(const int* __restrict__ ei) {
    int e = blockIdx.x * blockDim.x + threadIdx.x;
    if (e < EE) atomicAdd(&g_degi[ei[EE + e]], 1);
}

// Exclusive scan of degrees: per-block scan -> block sums -> add offsets.
__global__ void k_scanA() {
    __shared__ int sm[256];
    int i = blockIdx.x * 256 + threadIdx.x;
    int d = (i < NN) ? g_degi[i] : 0;
    int v = d;
    sm[threadIdx.x] = v; __syncthreads();
#pragma unroll
    for (int o = 1; o < 256; o <<= 1) {
        int t = (threadIdx.x >= o) ? sm[threadIdx.x - o] : 0;
        __syncthreads();
        v += t; sm[threadIdx.x] = v;
        __syncthreads();
    }
    if (i < NN) g_rp[i] = v - d;
    if (threadIdx.x == 255) g_bsum[blockIdx.x] = v;
}
__global__ void k_scanB(int nblk) {
    __shared__ int sm[256];
    int t = threadIdx.x;
    int d = (t < nblk) ? g_bsum[t] : 0;
    int v = d;
    sm[t] = v; __syncthreads();
#pragma unroll
    for (int o = 1; o < 256; o <<= 1) {
        int u = (t >= o) ? sm[t - o] : 0;
        __syncthreads();
        v += u; sm[t] = v;
        __syncthreads();
    }
    if (t < nblk) g_boff[t] = v - d;
}
__global__ void k_scanC() {
    int i = blockIdx.x * 256 + threadIdx.x;
    if (i < NN) g_rp[i] += g_boff[i >> 8];
}

// CSR fill + layer-1 feature scatter fused (one pass over edges)
__global__ void k_fillscat(const int* __restrict__ ei,
                           const float* __restrict__ x) {
    int e = blockIdx.x * blockDim.x + threadIdx.x;
    if (e >= EE) return;
    int s = ei[e], d = ei[EE + e];
    int p = atomicAdd(&g_cur[d], 1);
    g_csr[g_rp[d] + p] = s;
    const float* xr = x + s * 5;
    float4 v = make_float4(__ldg(xr), __ldg(xr + 1), __ldg(xr + 2), __ldg(xr + 3));
    red_add_v4(&g_agg[d * 8], v);
    atomicAdd(&g_agg[d * 8 + 4], __ldg(xr + 4));
}

// Layer 1 combine: h1 = relu(mean5 @ W1l^T + b1 + x @ W1r^T)
__global__ void k_combine1(const float* __restrict__ x,
                           const float* __restrict__ W1l,
                           const float* __restrict__ b1,
                           const float* __restrict__ W1r) {
    int t = blockIdx.x * blockDim.x + threadIdx.x;
    if (t >= NN * 64) return;
    int i = t >> 6, j = t & 63;
    float invd = 1.0f / fmaxf((float)g_degi[i], 1.0f);
    float acc = __ldg(&b1[j]);
#pragma unroll
    for (int c = 0; c < 5; c++) {
        acc = fmaf(g_agg[i * 8 + c] * invd, __ldg(&W1l[j * 5 + c]), acc);
        acc = fmaf(__ldg(&x[i * 5 + c]), __ldg(&W1r[j * 5 + c]), acc);
    }
    g_h1[t] = fmaxf(acc, 0.f);
}

// Layer 2 aggregation: warp per node, float4 lanes, 2 neighbors per step.
// Lanes 0-15 process even-step neighbor, lanes 16-31 odd; shfl_xor(16) combines.
__global__ void k_agg64() {
    int w = (blockIdx.x * blockDim.x + threadIdx.x) >> 5;
    if (w >= NN) return;
    int lane = threadIdx.x & 31;
    int half = lane >> 4, li = lane & 15;
    int beg = g_rp[w], deg = g_degi[w];
    const float4* h1v = (const float4*)g_h1;   // 16 float4 per node row
    float4 a = make_float4(0.f, 0.f, 0.f, 0.f);
    for (int base = 0; base < deg; base += 32) {
        int n = min(32, deg - base);
        int idx = (base + lane < deg) ? g_csr[beg + base + lane] : 0;
#pragma unroll 4
        for (int k = 0; k < n; k += 2) {
            int kk = k + half;
            int s = __shfl_sync(0xffffffffu, idx, kk);
            if (kk < n) {
                float4 v = h1v[s * 16 + li];
                a.x += v.x; a.y += v.y; a.z += v.z; a.w += v.w;
            }
        }
    }
    a.x += __shfl_xor_sync(0xffffffffu, a.x, 16);
    a.y += __shfl_xor_sync(0xffffffffu, a.y, 16);
    a.z += __shfl_xor_sync(0xffffffffu, a.z, 16);
    a.w += __shfl_xor_sync(0xffffffffu, a.w, 16);
    if (lane < 16) {
        float invd = 1.0f / fmaxf((float)deg, 1.0f);
        a.x *= invd; a.y *= invd; a.z *= invd; a.w *= invd;
        ((float4*)g_agg)[w * 16 + li] = a;
    }
}

// 64->64 combine; 100 nodes per block.
__global__ void k_combine64(const float* __restrict__ Wl,
                            const float* __restrict__ b,
                            const float* __restrict__ Wr) {
    __shared__ float sWl[64 * 64];
    __shared__ float sWr[64 * 64];
    __shared__ float sIn[4][64];
    __shared__ float sAg[4][64];
    int tid = threadIdx.x;
    for (int k = tid; k < 4096; k += 256) {
        int j = k >> 6, c = k & 63;
        sWl[c * 64 + j] = Wl[k];
        sWr[c * 64 + j] = Wr[k];
    }
    int g = tid >> 6, j = tid & 63;
    float bj = __ldg(&b[j]);
    for (int it = 0; it < 25; it++) {
        int node = (blockIdx.x * 25 + it) * 4 + g;
        __syncthreads();
        sIn[g][j] = g_h1[node * 64 + j];
        sAg[g][j] = g_agg[node * 64 + j];
        __syncthreads();
        float acc = bj;
#pragma unroll
        for (int c = 0; c < 64; c++) {
            acc = fmaf(sAg[g][c], sWl[c * 64 + j], acc);
            acc = fmaf(sIn[g][c], sWr[c * 64 + j], acc);
        }
        g_h2[node * 64 + j] = fmaxf(acc, 0.f);
    }
}

// Layer 3 pre-transform: t = h2 @ W3l^T. 80 nodes per block.
__global__ void k_t3(const float* __restrict__ W3l) {
    __shared__ float sW[64 * 32];
    __shared__ float sIn[8][64];
    int tid = threadIdx.x;
    for (int k = tid; k < 2048; k += 256) {
        int j = k >> 6, c = k & 63;
        sW[c * 32 + j] = W3l[k];
    }
    int g = tid >> 5, j = tid & 31;
    for (int it = 0; it < 10; it++) {
        int node0 = (blockIdx.x * 10 + it) * 8;
        __syncthreads();
        for (int k = tid; k < 512; k += 256) {
            int gg = k >> 6, c = k & 63;
            sIn[gg][c] = g_h2[(node0 + gg) * 64 + c];
        }
        __syncthreads();
        float acc = 0.f;
#pragma unroll
        for (int c = 0; c < 64; c++)
            acc = fmaf(sIn[g][c], sW[c * 32 + j], acc);
        g_t[(node0 + g) * 32 + j] = acc;
    }
}

// Layer 3 aggregation: warp per node, float4 lanes, 4 neighbors per step.
__global__ void k_agg32() {
    int w = (blockIdx.x * blockDim.x + threadIdx.x) >> 5;
    if (w >= NN) return;
    int lane = threadIdx.x & 31;
    int q = lane >> 3, li = lane & 7;
    int beg = g_rp[w], deg = g_degi[w];
    const float4* tv = (const float4*)g_t;     // 8 float4 per node row
    float4 a = make_float4(0.f, 0.f, 0.f, 0.f);
    for (int base = 0; base < deg; base += 32) {
        int n = min(32, deg - base);
        int idx = (base + lane < deg) ? g_csr[beg + base + lane] : 0;
#pragma unroll 2
        for (int k = 0; k < n; k += 4) {
            int kk = k + q;
            int s = __shfl_sync(0xffffffffu, idx, kk);
            if (kk < n) {
                float4 v = tv[s * 8 + li];
                a.x += v.x; a.y += v.y; a.z += v.z; a.w += v.w;
            }
        }
    }
#pragma unroll
    for (int m = 8; m <= 16; m <<= 1) {
        a.x += __shfl_xor_sync(0xffffffffu, a.x, m);
        a.y += __shfl_xor_sync(0xffffffffu, a.y, m);
        a.z += __shfl_xor_sync(0xffffffffu, a.z, m);
        a.w += __shfl_xor_sync(0xffffffffu, a.w, m);
    }
    if (lane < 8) {
        float invd = 1.0f / fmaxf((float)deg, 1.0f);
        a.x *= invd; a.y *= invd; a.z *= invd; a.w *= invd;
        ((float4*)g_agg)[w * 8 + li] = a;
    }
}

// Final: out = mean32 + b3 + h2 @ W3r^T. 80 nodes per block.
__global__ void k_final(const float* __restrict__ b3,
                        const float* __restrict__ W3r,
                        float* __restrict__ out) {
    __shared__ float sW[64 * 32];
    __shared__ float sIn[8][64];
    int tid = threadIdx.x;
    for (int k = tid; k < 2048; k += 256) {
        int j = k >> 6, c = k & 63;
        sW[c * 32 + j] = W3r[k];
    }
    int g = tid >> 5, j = tid & 31;
    float bj = __ldg(&b3[j]);
    for (int it = 0; it < 10; it++) {
        int node0 = (blockIdx.x * 10 + it) * 8;
        __syncthreads();
        for (int k = tid; k < 512; k += 256) {
            int gg = k >> 6, c = k & 63;
            sIn[gg][c] = g_h2[(node0 + gg) * 64 + c];
        }
        __syncthreads();
        int node = node0 + g;
        float acc = bj + g_agg[node * 32 + j];
#pragma unroll
        for (int c = 0; c < 64; c++)
            acc = fmaf(sIn[g][c], sW[c * 32 + j], acc);
        out[node * 32 + j] = acc;
    }
}

// ---------------------------------------------------------------------------
extern "C" void kernel_launch(void* const* d_in, const int* in_sizes, int n_in,
                              void* d_out, int out_size) {
    const float* x   = (const float*)d_in[0];
    const int*   ei  = (const int*)d_in[1];
    const float* W1l = (const float*)d_in[2];
    const float* b1  = (const float*)d_in[3];
    const float* W1r = (const float*)d_in[4];
    const float* W2l = (const float*)d_in[5];
    const float* b2  = (const float*)d_in[6];
    const float* W2r = (const float*)d_in[7];
    const float* W3l = (const float*)d_in[8];
    const float* b3  = (const float*)d_in[9];
    const float* W3r = (const float*)d_in[10];
    float* out = (float*)d_out;

    const int T = 256;
    const int SCAN_BLKS = (NN + 255) / 256;   // 196

    k_init<<<(NN * 8 + T - 1) / T, T>>>();
    k_degi<<<(EE + T - 1) / T, T>>>(ei);
    k_scanA<<<SCAN_BLKS, 256>>>();
    k_scanB<<<1, 256>>>(SCAN_BLKS);
    k_scanC<<<SCAN_BLKS, 256>>>();
    k_fillscat<<<(EE + T - 1) / T, T>>>(ei, x);

    // layer 1
    k_combine1<<<(NN * 64 + T - 1) / T, T>>>(x, W1l, b1, W1r);

    // layer 2
    k_agg64<<<(NN * 32 + T - 1) / T, T>>>();
    k_combine64<<<NN / 100, T>>>(W2l, b2, W2r);  // 500 blocks

    // layer 3
    k_t3<<<NN / 80, T>>>(W3l);                   // 625 blocks
    k_agg32<<<(NN * 32 + T - 1) / T, T>>>();
    k_final<<<NN / 80, T>>>(b3, W3r, out);       // 625 blocks
}

// round 7
// speedup vs baseline: 1.5307x; 1.5307x over previous
#include <cuda_runtime.h>

#define NN 50000
#define EE 800000

// Scratch (allocation-free: __device__ globals)
__device__ float g_h1[NN * 64];
__device__ float g_h2[NN * 64];
__device__ float g_agg[NN * 64];   // layer1: stride-8 atomic target; layer2/3: mean store
__device__ float g_t[NN * 32];
__device__ int   g_degi[NN];
__device__ int   g_cur[NN];
__device__ int   g_rp[NN];         // CSR row start (exclusive prefix of deg)
__device__ int   g_bsum[256];
__device__ int   g_boff[256];
__device__ int   g_csr[EE];        // src node per CSR slot

__device__ __forceinline__ void red_add_v4(float* addr, float4 v) {
    asm volatile("red.global.add.v4.f32 [%0], {%1,%2,%3,%4};"
                 :: "l"(addr), "f"(v.x), "f"(v.y), "f"(v.z), "f"(v.w)
                 : "memory");
}

// ---------------------------------------------------------------------------
__global__ void k_init() {
    int i = blockIdx.x * blockDim.x + threadIdx.x;
    if (i < NN * 8) g_agg[i] = 0.f;
    if (i < NN) { g_degi[i] = 0; g_cur[i] = 0; }
}

__global__ void k_degi(const int* __restrict__ ei) {
    int e = blockIdx.x * blockDim.x + threadIdx.x;
    if (e < EE) atomicAdd(&g_degi[ei[EE + e]], 1);
}

// Exclusive scan of degrees: per-block scan -> block sums -> add offsets.
__global__ void k_scanA() {
    __shared__ int sm[256];
    int i = blockIdx.x * 256 + threadIdx.x;
    int d = (i < NN) ? g_degi[i] : 0;
    int v = d;
    sm[threadIdx.x] = v; __syncthreads();
#pragma unroll
    for (int o = 1; o < 256; o <<= 1) {
        int t = (threadIdx.x >= o) ? sm[threadIdx.x - o] : 0;
        __syncthreads();
        v += t; sm[threadIdx.x] = v;
        __syncthreads();
    }
    if (i < NN) g_rp[i] = v - d;
    if (threadIdx.x == 255) g_bsum[blockIdx.x] = v;
}
__global__ void k_scanB(int nblk) {
    __shared__ int sm[256];
    int t = threadIdx.x;
    int d = (t < nblk) ? g_bsum[t] : 0;
    int v = d;
    sm[t] = v; __syncthreads();
#pragma unroll
    for (int o = 1; o < 256; o <<= 1) {
        int u = (t >= o) ? sm[t - o] : 0;
        __syncthreads();
        v += u; sm[t] = v;
        __syncthreads();
    }
    if (t < nblk) g_boff[t] = v - d;
}
__global__ void k_scanC() {
    int i = blockIdx.x * 256 + threadIdx.x;
    if (i < NN) g_rp[i] += g_boff[i >> 8];
}

// CSR fill + layer-1 feature scatter fused (one pass over edges)
__global__ void k_fillscat(const int* __restrict__ ei,
                           const float* __restrict__ x) {
    int e = blockIdx.x * blockDim.x + threadIdx.x;
    if (e >= EE) return;
    int s = ei[e], d = ei[EE + e];
    int p = atomicAdd(&g_cur[d], 1);
    g_csr[g_rp[d] + p] = s;
    const float* xr = x + s * 5;
    float4 v = make_float4(__ldg(xr), __ldg(xr + 1), __ldg(xr + 2), __ldg(xr + 3));
    red_add_v4(&g_agg[d * 8], v);
    atomicAdd(&g_agg[d * 8 + 4], __ldg(xr + 4));
}

// Layer 1 combine: h1 = relu(mean5 @ W1l^T + b1 + x @ W1r^T)
__global__ void k_combine1(const float* __restrict__ x,
                           const float* __restrict__ W1l,
                           const float* __restrict__ b1,
                           const float* __restrict__ W1r) {
    int t = blockIdx.x * blockDim.x + threadIdx.x;
    if (t >= NN * 64) return;
    int i = t >> 6, j = t & 63;
    float invd = 1.0f / fmaxf((float)g_degi[i], 1.0f);
    float acc = __ldg(&b1[j]);
#pragma unroll
    for (int c = 0; c < 5; c++) {
        acc = fmaf(g_agg[i * 8 + c] * invd, __ldg(&W1l[j * 5 + c]), acc);
        acc = fmaf(__ldg(&x[i * 5 + c]), __ldg(&W1r[j * 5 + c]), acc);
    }
    g_h1[t] = fmaxf(acc, 0.f);
}

// Layer 2 aggregation: warp per node, CSR gather (R5-proven form).
// Lane handles 2 channels (float2); per neighbor the warp reads one 256B row.
__global__ void k_agg64() {
    int w = (blockIdx.x * blockDim.x + threadIdx.x) >> 5;
    if (w >= NN) return;
    int lane = threadIdx.x & 31;
    int beg = g_rp[w], deg = g_degi[w];
    const float2* h1v = (const float2*)g_h1;
    float ax = 0.f, ay = 0.f;
    for (int base = 0; base < deg; base += 32) {
        int n = min(32, deg - base);
        int idx = (base + lane < deg) ? g_csr[beg + base + lane] : 0;
#pragma unroll 8
        for (int k = 0; k < n; k++) {
            int s = __shfl_sync(0xffffffffu, idx, k);
            float2 v = h1v[s * 32 + lane];
            ax += v.x; ay += v.y;
        }
    }
    float invd = 1.0f / fmaxf((float)deg, 1.0f);
    ((float2*)g_agg)[w * 32 + lane] = make_float2(ax * invd, ay * invd);
}

// 64->64 combine; 100 nodes per block.
__global__ void k_combine64(const float* __restrict__ Wl,
                            const float* __restrict__ b,
                            const float* __restrict__ Wr) {
    __shared__ float sWl[64 * 64];
    __shared__ float sWr[64 * 64];
    __shared__ float sIn[4][64];
    __shared__ float sAg[4][64];
    int tid = threadIdx.x;
    for (int k = tid; k < 4096; k += 256) {
        int j = k >> 6, c = k & 63;
        sWl[c * 64 + j] = Wl[k];
        sWr[c * 64 + j] = Wr[k];
    }
    int g = tid >> 6, j = tid & 63;
    float bj = __ldg(&b[j]);
    for (int it = 0; it < 25; it++) {
        int node = (blockIdx.x * 25 + it) * 4 + g;
        __syncthreads();
        sIn[g][j] = g_h1[node * 64 + j];
        sAg[g][j] = g_agg[node * 64 + j];   // already mean-scaled
        __syncthreads();
        float acc = bj;
#pragma unroll
        for (int c = 0; c < 64; c++) {
            acc = fmaf(sAg[g][c], sWl[c * 64 + j], acc);
            acc = fmaf(sIn[g][c], sWr[c * 64 + j], acc);
        }
        g_h2[node * 64 + j] = fmaxf(acc, 0.f);
    }
}

// Layer 3 pre-transform: t = h2 @ W3l^T. 80 nodes per block.
__global__ void k_t3(const float* __restrict__ W3l) {
    __shared__ float sW[64 * 32];
    __shared__ float sIn[8][64];
    int tid = threadIdx.x;
    for (int k = tid; k < 2048; k += 256) {
        int j = k >> 6, c = k & 63;
        sW[c * 32 + j] = W3l[k];
    }
    int g = tid >> 5, j = tid & 31;
    for (int it = 0; it < 10; it++) {
        int node0 = (blockIdx.x * 10 + it) * 8;
        __syncthreads();
        for (int k = tid; k < 512; k += 256) {
            int gg = k >> 6, c = k & 63;
            sIn[gg][c] = g_h2[(node0 + gg) * 64 + c];
        }
        __syncthreads();
        float acc = 0.f;
#pragma unroll
        for (int c = 0; c < 64; c++)
            acc = fmaf(sIn[g][c], sW[c * 32 + j], acc);
        g_t[(node0 + g) * 32 + j] = acc;
    }
}

// Layer 3 aggregation: warp per node, lane = channel (R5-proven form).
__global__ void k_agg32() {
    int w = (blockIdx.x * blockDim.x + threadIdx.x) >> 5;
    if (w >= NN) return;
    int lane = threadIdx.x & 31;
    int beg = g_rp[w], deg = g_degi[w];
    float acc = 0.f;
    for (int base = 0; base < deg; base += 32) {
        int n = min(32, deg - base);
        int idx = (base + lane < deg) ? g_csr[beg + base + lane] : 0;
#pragma unroll 8
        for (int k = 0; k < n; k++) {
            int s = __shfl_sync(0xffffffffu, idx, k);
            acc += g_t[s * 32 + lane];
        }
    }
    g_agg[w * 32 + lane] = acc * (1.0f / fmaxf((float)deg, 1.0f));
}

// Final: out = mean32 + b3 + h2 @ W3r^T. 80 nodes per block.
__global__ void k_final(const float* __restrict__ b3,
                        const float* __restrict__ W3r,
                        float* __restrict__ out) {
    __shared__ float sW[64 * 32];
    __shared__ float sIn[8][64];
    int tid = threadIdx.x;
    for (int k = tid; k < 2048; k += 256) {
        int j = k >> 6, c = k & 63;
        sW[c * 32 + j] = W3r[k];
    }
    int g = tid >> 5, j = tid & 31;
    float bj = __ldg(&b3[j]);
    for (int it = 0; it < 10; it++) {
        int node0 = (blockIdx.x * 10 + it) * 8;
        __syncthreads();
        for (int k = tid; k < 512; k += 256) {
            int gg = k >> 6, c = k & 63;
            sIn[gg][c] = g_h2[(node0 + gg) * 64 + c];
        }
        __syncthreads();
        int node = node0 + g;
        float acc = bj + g_agg[node * 32 + j];
#pragma unroll
        for (int c = 0; c < 64; c++)
            acc = fmaf(sIn[g][c], sW[c * 32 + j], acc);
        out[node * 32 + j] = acc;
    }
}

// ---------------------------------------------------------------------------
extern "C" void kernel_launch(void* const* d_in, const int* in_sizes, int n_in,
                              void* d_out, int out_size) {
    const float* x   = (const float*)d_in[0];
    const int*   ei  = (const int*)d_in[1];
    const float* W1l = (const float*)d_in[2];
    const float* b1  = (const float*)d_in[3];
    const float* W1r = (const float*)d_in[4];
    const float* W2l = (const float*)d_in[5];
    const float* b2  = (const float*)d_in[6];
    const float* W2r = (const float*)d_in[7];
    const float* W3l = (const float*)d_in[8];
    const float* b3  = (const float*)d_in[9];
    const float* W3r = (const float*)d_in[10];
    float* out = (float*)d_out;

    const int T = 256;
    const int SCAN_BLKS = (NN + 255) / 256;   // 196

    k_init<<<(NN * 8 + T - 1) / T, T>>>();
    k_degi<<<(EE + T - 1) / T, T>>>(ei);
    k_scanA<<<SCAN_BLKS, 256>>>();
    k_scanB<<<1, 256>>>(SCAN_BLKS);
    k_scanC<<<SCAN_BLKS, 256>>>();
    k_fillscat<<<(EE + T - 1) / T, T>>>(ei, x);

    // layer 1
    k_combine1<<<(NN * 64 + T - 1) / T, T>>>(x, W1l, b1, W1r);

    // layer 2
    k_agg64<<<(NN * 32 + T - 1) / T, T>>>();
    k_combine64<<<NN / 100, T>>>(W2l, b2, W2r);  // 500 blocks

    // layer 3
    k_t3<<<NN / 80, T>>>(W3l);                   // 625 blocks
    k_agg32<<<(NN * 32 + T - 1) / T, T>>>();
    k_final<<<NN / 80, T>>>(b3, W3r, out);       // 625 blocks
}